// round 17
// baseline (speedup 1.0000x reference)
#include <cuda_runtime.h>

#define BSZ 8
#define SEQ 4096
#define NH 32
#define HD 128
#define QLR 1536
#define NQ (NH*HD)      // 4096
#define KVROW (NH*256)  // floats per (b,s) row = 8192
#define NCHUNK 8
#define CHUNK (SEQ/NCHUNK)   // 512

#define RB 8             // r-split blocks for qproj
#define CB 32            // col blocks (128 cols each)
#define RPB (QLR/RB)     // 192 rows per block
#define RPW (RPB/8)      // 24 rows per warp
#define BT 8             // rows per load batch

// Device-global scratch (no allocation allowed)
__device__ __align__(16) float g_qpart[RB * BSZ * NQ];        // 1 MB split-K partials
__device__ __align__(16) float g_po[BSZ * NH * NCHUNK * HD];  // unnormalized partial outputs
__device__ float g_pm[BSZ * NH * NCHUNK];                     // partial max
__device__ float g_ps[BSZ * NH * NCHUNK];                     // partial expsum

// ---------------------------------------------------------------------------
__device__ __forceinline__ void fma_batch(const float4* __restrict__ buf,
                                          const float (*hs_s)[BSZ],
                                          int rbase, float4* acc)
{
#pragma unroll
    for (int j = 0; j < BT; ++j) {
        const float4 h0 = *(const float4*)(&hs_s[rbase + j][0]);  // b 0..3
        const float4 h1 = *(const float4*)(&hs_s[rbase + j][4]);  // b 4..7
        const float4 w4 = buf[j];
        acc[0].x += h0.x * w4.x; acc[0].y += h0.x * w4.y; acc[0].z += h0.x * w4.z; acc[0].w += h0.x * w4.w;
        acc[1].x += h0.y * w4.x; acc[1].y += h0.y * w4.y; acc[1].z += h0.y * w4.z; acc[1].w += h0.y * w4.w;
        acc[2].x += h0.z * w4.x; acc[2].y += h0.z * w4.y; acc[2].z += h0.z * w4.z; acc[2].w += h0.z * w4.w;
        acc[3].x += h0.w * w4.x; acc[3].y += h0.w * w4.y; acc[3].z += h0.w * w4.z; acc[3].w += h0.w * w4.w;
        acc[4].x += h1.x * w4.x; acc[4].y += h1.x * w4.y; acc[4].z += h1.x * w4.z; acc[4].w += h1.x * w4.w;
        acc[5].x += h1.y * w4.x; acc[5].y += h1.y * w4.y; acc[5].z += h1.y * w4.z; acc[5].w += h1.y * w4.w;
        acc[6].x += h1.z * w4.x; acc[6].y += h1.z * w4.y; acc[6].z += h1.z * w4.z; acc[6].w += h1.z * w4.w;
        acc[7].x += h1.w * w4.x; acc[7].y += h1.w * w4.y; acc[7].z += h1.w * w4.z; acc[7].w += h1.w * w4.w;
    }
}

// ---------------------------------------------------------------------------
// qproj stage 1: split-K streaming GEMM. grid = CB*RB = 256 CTAs x 256 thr.
// ---------------------------------------------------------------------------
__global__ __launch_bounds__(256, 2) void qproj1_kernel(const float* __restrict__ hs,
                                                        const float* __restrict__ W)
{
    __shared__ float4 part[8][BSZ][32];   // [warp][b][col4] = 32 KB
    __shared__ float  hs_s[RPB][BSZ];     // 6 KB, [r][b]

    const int cb   = blockIdx.x & (CB - 1);
    const int rb   = blockIdx.x >> 5;
    const int tid  = threadIdx.x;
    const int w    = tid >> 5;
    const int lane = tid & 31;

    const int n4 = cb * 128 + lane * 4;
    const int r0 = rb * RPB;

    for (int idx = tid; idx < (RPB / 4) * BSZ; idx += 256) {
        const int b = idx / (RPB / 4);
        const int i = idx % (RPB / 4);
        const float4 v = *(const float4*)(&hs[b * QLR + r0 + 4 * i]);
        hs_s[4 * i + 0][b] = v.x;
        hs_s[4 * i + 1][b] = v.y;
        hs_s[4 * i + 2][b] = v.z;
        hs_s[4 * i + 3][b] = v.w;
    }
    __syncthreads();

    const int rw = w * RPW;
    const float* Wb = &W[(size_t)(r0 + rw) * NQ + n4];

    float4 bufA[BT], bufB[BT];
#pragma unroll
    for (int j = 0; j < BT; ++j) bufA[j] = *(const float4*)(Wb + (size_t)j * NQ);
#pragma unroll
    for (int j = 0; j < BT; ++j) bufB[j] = *(const float4*)(Wb + (size_t)(BT + j) * NQ);

    float4 acc[BSZ];
#pragma unroll
    for (int b = 0; b < BSZ; ++b) acc[b] = make_float4(0.f, 0.f, 0.f, 0.f);

    fma_batch(bufA, hs_s, rw, acc);
#pragma unroll
    for (int j = 0; j < BT; ++j) bufA[j] = *(const float4*)(Wb + (size_t)(2 * BT + j) * NQ);
    fma_batch(bufB, hs_s, rw + BT, acc);
    fma_batch(bufA, hs_s, rw + 2 * BT, acc);

#pragma unroll
    for (int b = 0; b < BSZ; ++b) part[w][b][lane] = acc[b];
    __syncthreads();

    {
        const int b2 = tid >> 5;
        const int l2 = tid & 31;
        float4 s = part[0][b2][l2];
#pragma unroll
        for (int ww = 1; ww < 8; ++ww) {
            const float4 t = part[ww][b2][l2];
            s.x += t.x; s.y += t.y; s.z += t.z; s.w += t.w;
        }
        *(float4*)(&g_qpart[((size_t)rb * BSZ + b2) * NQ + cb * 128 + l2 * 4]) = s;
    }
}

// ---------------------------------------------------------------------------
// attention: split-KV, software-pipelined loads. grid = 2048 CTAs x 256 thr.
// ---------------------------------------------------------------------------
__global__ __launch_bounds__(256) void attn_kernel(const float* __restrict__ kv,
                                                   const float* __restrict__ bq)
{
    __shared__ float  sc[CHUNK];          // 2 KB
    __shared__ float4 part[8][32];        // 4 KB
    __shared__ float  red[8];
    __shared__ float  qsm[HD];

    const int id   = blockIdx.x;          // (b*NH + h)*NCHUNK + c
    const int c    = id & (NCHUNK - 1);
    const int bh   = id / NCHUNK;
    const int b    = bh >> 5;
    const int h    = bh & 31;
    const int tid  = threadIdx.x;
    const int w    = tid >> 5;
    const int lane = tid & 31;

    // ---------------- Prologue: reduce split-K q partials + bias ----------
    if (tid < 32) {
        const int n = h * HD + 4 * tid;
        float4 s = *(const float4*)(&bq[n]);
#pragma unroll
        for (int rb = 0; rb < RB; ++rb) {
            const float4 t = *(const float4*)(&g_qpart[((size_t)rb * BSZ + b) * NQ + n]);
            s.x += t.x; s.y += t.y; s.z += t.z; s.w += t.w;
        }
        *(float4*)(&qsm[4 * tid]) = s;
    }
    __syncthreads();

    const float4 qv = *(const float4*)(&qsm[4 * lane]);
    const float* kvb = kv + ((size_t)(b * SEQ + c * CHUNK) * NH + h) * 256;
    const float* kp  = kvb + (size_t)w * KVROW + 4 * lane;   // warp's K stream base

    // ---------------- Pass 1: scores (pipelined: prefetch i+1 first) ------
    {
        float4 k0 = *(const float4*)(kp + (size_t)( 0) * KVROW);
        float4 k1 = *(const float4*)(kp + (size_t)( 8) * KVROW);
        float4 k2 = *(const float4*)(kp + (size_t)(16) * KVROW);
        float4 k3 = *(const float4*)(kp + (size_t)(24) * KVROW);
#pragma unroll
        for (int i = 0; i < CHUNK / 32; ++i) {
            float4 n0, n1, n2, n3;
            if (i + 1 < CHUNK / 32) {
                n0 = *(const float4*)(kp + (size_t)(32*(i+1) +  0) * KVROW);
                n1 = *(const float4*)(kp + (size_t)(32*(i+1) +  8) * KVROW);
                n2 = *(const float4*)(kp + (size_t)(32*(i+1) + 16) * KVROW);
                n3 = *(const float4*)(kp + (size_t)(32*(i+1) + 24) * KVROW);
            }
            const float d0 = k0.x*qv.x + k0.y*qv.y + k0.z*qv.z + k0.w*qv.w;
            const float d1 = k1.x*qv.x + k1.y*qv.y + k1.z*qv.z + k1.w*qv.w;
            const float d2 = k2.x*qv.x + k2.y*qv.y + k2.z*qv.z + k2.w*qv.w;
            const float d3 = k3.x*qv.x + k3.y*qv.y + k3.z*qv.z + k3.w*qv.w;

            const float a0 = d0 + __shfl_xor_sync(0xffffffffu, d0, 16);
            const float a1 = d1 + __shfl_xor_sync(0xffffffffu, d1, 16);
            const float a2 = d2 + __shfl_xor_sync(0xffffffffu, d2, 16);
            const float a3 = d3 + __shfl_xor_sync(0xffffffffu, d3, 16);
            float m0 = (lane & 16) ? a1 : a0;
            float m1 = (lane & 16) ? a3 : a2;
            m0 += __shfl_xor_sync(0xffffffffu, m0, 8);
            m1 += __shfl_xor_sync(0xffffffffu, m1, 8);
            float n = (lane & 8) ? m1 : m0;
            n += __shfl_xor_sync(0xffffffffu, n, 4);
            n += __shfl_xor_sync(0xffffffffu, n, 2);
            n += __shfl_xor_sync(0xffffffffu, n, 1);
            if ((lane & 7) == 0) {
                const int j = ((lane >> 4) & 1) | (((lane >> 3) & 1) << 1);
                sc[w + 8 * j + 32 * i] = n;
            }
            k0 = n0; k1 = n1; k2 = n2; k3 = n3;
        }
    }
    __syncthreads();

    // ---------------- Local softmax stats ----------------
    float m = -1e30f;
#pragma unroll
    for (int k = 0; k < CHUNK / 256; ++k)
        m = fmaxf(m, sc[tid + 256 * k]);
    m = fmaxf(m, __shfl_xor_sync(0xffffffffu, m, 16));
    m = fmaxf(m, __shfl_xor_sync(0xffffffffu, m, 8));
    m = fmaxf(m, __shfl_xor_sync(0xffffffffu, m, 4));
    m = fmaxf(m, __shfl_xor_sync(0xffffffffu, m, 2));
    m = fmaxf(m, __shfl_xor_sync(0xffffffffu, m, 1));
    if (lane == 0) red[w] = m;
    __syncthreads();

    float gmax = red[0];
#pragma unroll
    for (int ww = 1; ww < 8; ++ww) gmax = fmaxf(gmax, red[ww]);

    float lsum = 0.f;
#pragma unroll
    for (int k = 0; k < CHUNK / 256; ++k) {
        const float e = __expf(sc[tid + 256 * k] - gmax);
        sc[tid + 256 * k] = e;
        lsum += e;
    }
    lsum += __shfl_xor_sync(0xffffffffu, lsum, 16);
    lsum += __shfl_xor_sync(0xffffffffu, lsum, 8);
    lsum += __shfl_xor_sync(0xffffffffu, lsum, 4);
    lsum += __shfl_xor_sync(0xffffffffu, lsum, 2);
    lsum += __shfl_xor_sync(0xffffffffu, lsum, 1);
    __syncthreads();                  // done reading red (gmax)
    if (lane == 0) red[w] = lsum;
    __syncthreads();

    float total = red[0];
#pragma unroll
    for (int ww = 1; ww < 8; ++ww) total += red[ww];

    // ---------------- Pass 2: unnormalized output (pipelined) -------------
    float4 acc0 = make_float4(0.f, 0.f, 0.f, 0.f);
    float4 acc1 = make_float4(0.f, 0.f, 0.f, 0.f);
    {
        const float* vp = kvb + 128 + (size_t)w * KVROW + 4 * lane;
        float4 v0 = *(const float4*)(vp + (size_t)( 0) * KVROW);
        float4 v1 = *(const float4*)(vp + (size_t)( 8) * KVROW);
        float4 v2 = *(const float4*)(vp + (size_t)(16) * KVROW);
        float4 v3 = *(const float4*)(vp + (size_t)(24) * KVROW);
        float  p0 = sc[w +  0], p1 = sc[w +  8], p2 = sc[w + 16], p3 = sc[w + 24];
#pragma unroll
        for (int i = 0; i < CHUNK / 32; ++i) {
            float4 w0, w1, w2, w3;
            float  q0, q1, q2, q3;
            if (i + 1 < CHUNK / 32) {
                w0 = *(const float4*)(vp + (size_t)(32*(i+1) +  0) * KVROW);
                w1 = *(const float4*)(vp + (size_t)(32*(i+1) +  8) * KVROW);
                w2 = *(const float4*)(vp + (size_t)(32*(i+1) + 16) * KVROW);
                w3 = *(const float4*)(vp + (size_t)(32*(i+1) + 24) * KVROW);
                q0 = sc[w + 32*(i+1) +  0];
                q1 = sc[w + 32*(i+1) +  8];
                q2 = sc[w + 32*(i+1) + 16];
                q3 = sc[w + 32*(i+1) + 24];
            }
            acc0.x += p0 * v0.x; acc0.y += p0 * v0.y; acc0.z += p0 * v0.z; acc0.w += p0 * v0.w;
            acc1.x += p1 * v1.x; acc1.y += p1 * v1.y; acc1.z += p1 * v1.z; acc1.w += p1 * v1.w;
            acc0.x += p2 * v2.x; acc0.y += p2 * v2.y; acc0.z += p2 * v2.z; acc0.w += p2 * v2.w;
            acc1.x += p3 * v3.x; acc1.y += p3 * v3.y; acc1.z += p3 * v3.z; acc1.w += p3 * v3.w;
            v0 = w0; v1 = w1; v2 = w2; v3 = w3;
            p0 = q0; p1 = q1; p2 = q2; p3 = q3;
        }
    }
    acc0.x += acc1.x; acc0.y += acc1.y; acc0.z += acc1.z; acc0.w += acc1.w;
    part[w][lane] = acc0;
    __syncthreads();

    if (tid < 32) {
        float4 r = part[0][tid];
#pragma unroll
        for (int ww = 1; ww < 8; ++ww) {
            const float4 t = part[ww][tid];
            r.x += t.x; r.y += t.y; r.z += t.z; r.w += t.w;
        }
        *(float4*)(&g_po[(size_t)id * HD + 4 * tid]) = r;   // unnormalized
        if (tid == 0) { g_pm[id] = gmax; g_ps[id] = total; }
    }
}

// ---------------------------------------------------------------------------
// combine: 64 blocks x 128 threads, one float4 of output per thread.
// ---------------------------------------------------------------------------
__global__ __launch_bounds__(128) void combine_kernel(float* __restrict__ out)
{
    const int idx = blockIdx.x * 128 + threadIdx.x;   // 0 .. 8191
    const int bh  = idx >> 5;                         // b*NH + h
    const int d4  = (idx & 31) * 4;
    const int i0  = bh * NCHUNK;

    float gm = g_pm[i0];
#pragma unroll
    for (int c = 1; c < NCHUNK; ++c) gm = fmaxf(gm, g_pm[i0 + c]);

    float den = 0.f;
    float4 num = make_float4(0.f, 0.f, 0.f, 0.f);
#pragma unroll
    for (int c = 0; c < NCHUNK; ++c) {
        const float e = __expf(g_pm[i0 + c] - gm);
        den += e * g_ps[i0 + c];
        const float4 t = *(const float4*)(&g_po[(size_t)(i0 + c) * HD + d4]);
        num.x += e * t.x; num.y += e * t.y; num.z += e * t.z; num.w += e * t.w;
    }
    const float inv = 1.f / den;
    num.x *= inv; num.y *= inv; num.z *= inv; num.w *= inv;
    *(float4*)(&out[(size_t)bh * HD + d4]) = num;
}

// ---------------------------------------------------------------------------
extern "C" void kernel_launch(void* const* d_in, const int* in_sizes, int n_in,
                              void* d_out, int out_size)
{
    const float* hs = (const float*)d_in[0];  // (8, 1536)
    const float* kv = (const float*)d_in[1];  // (8, 4096, 32, 256)
    const float* W  = (const float*)d_in[2];  // (1536, 4096)
    const float* bq = (const float*)d_in[3];  // (4096,)
    float* out = (float*)d_out;               // (8, 4096)

    qproj1_kernel<<<CB * RB, 256>>>(hs, W);
    attn_kernel<<<BSZ * NH * NCHUNK, 256>>>(kv, bq);
    combine_kernel<<<64, 128>>>(out);
}